// round 2
// baseline (speedup 1.0000x reference)
#include <cuda_runtime.h>

// Problem constants
#define BB   8
#define CC   256
#define HH   128
#define WW   128
#define CRED 64
#define HW   (HH * WW)

// Conv tiling: block = 256 threads, tile = 32 rows x 64 cols x 16 c_out
#define TCO      16
#define TH       32
#define TW       64
#define CICHUNK  4
#define XSTRIDE  68       // 66 halo cols padded to 68 (even -> 8B-aligned float2)

typedef unsigned long long u64;

__device__ float g_pool[BB * CC];
__device__ float g_scale[BB * CC];

__device__ __forceinline__ void ffma2(u64 &d, u64 a, u64 b) {
    asm("fma.rn.f32x2 %0, %1, %2, %0;" : "+l"(d) : "l"(a), "l"(b));
}
__device__ __forceinline__ u64 pack2(float lo, float hi) {
    u64 r; asm("mov.b64 %0, {%1, %2};" : "=l"(r) : "f"(lo), "f"(hi)); return r;
}
__device__ __forceinline__ float2 unpack2(u64 v) {
    float2 f; asm("mov.b64 {%0, %1}, %2;" : "=f"(f.x), "=f"(f.y) : "l"(v)); return f;
}

// ---------------------------------------------------------------------------
// Conv 3x3 pad 1, fp32 via packed FFMA2.
// Thread pixels: rows {ty, ty+16}, col pairs {2tx, 2tx+1} and {2tx+32, 2tx+33}.
// ---------------------------------------------------------------------------
__global__ __launch_bounds__(256, 1)
void conv3x3_kernel(const float* __restrict__ x,
                    const float* __restrict__ w,
                    const float* __restrict__ bias,
                    float* __restrict__ y)
{
    __shared__ float xs[CICHUNK][TH + 2][XSTRIDE];
    __shared__ u64   ws2[TCO][CICHUNK][9];          // weight duplicated (wv,wv)

    const int b   = blockIdx.z;
    const int co0 = blockIdx.y * TCO;
    const int h0  = (blockIdx.x >> 1) * TH;          // 4 vertical tiles
    const int w0  = (blockIdx.x & 1) * TW;           // 2 horizontal tiles

    const int tid = threadIdx.x;
    const int tx  = tid & 15;
    const int ty  = tid >> 4;
    const int cA  = 2 * tx;                          // col group A base (in-tile)
    const int cB  = 2 * tx + 32;                     // col group B base

    // acc[c][p]: p0=(rowA,gA) p1=(rowA,gB) p2=(rowB,gA) p3=(rowB,gB)
    u64 acc[TCO][4];
#pragma unroll
    for (int c = 0; c < TCO; c++)
#pragma unroll
        for (int p = 0; p < 4; p++) acc[c][p] = 0ull;

    for (int ci0 = 0; ci0 < CC; ci0 += CICHUNK) {
        // ---- stage input tile with halo (zero-padded) ----
        for (int idx = tid; idx < CICHUNK * (TH + 2) * 66; idx += 256) {
            int ci  = idx / ((TH + 2) * 66);
            int rem = idx % ((TH + 2) * 66);
            int r   = rem / 66;
            int cl  = rem % 66;
            int gh  = h0 - 1 + r;
            int gw  = w0 - 1 + cl;
            float v = 0.0f;
            if (gh >= 0 && gh < HH && gw >= 0 && gw < WW)
                v = x[(((long)b * CC + ci0 + ci) * HH + gh) * WW + gw];
            xs[ci][r][cl] = v;
        }
        // ---- stage duplicated weights ----
        for (int idx = tid; idx < TCO * CICHUNK * 9; idx += 256) {
            int co  = idx / (CICHUNK * 9);
            int rem = idx % (CICHUNK * 9);
            int ci  = rem / 9;
            int t   = rem % 9;
            float wv = w[((long)(co0 + co) * CC + ci0 + ci) * 9 + t];
            ws2[co][ci][t] = pack2(wv, wv);
        }
        __syncthreads();

#pragma unroll
        for (int ci = 0; ci < CICHUNK; ci++) {
#pragma unroll
            for (int kh = 0; kh < 3; kh++) {
                const float* rA = &xs[ci][ty + kh][0];
                const float* rB = &xs[ci][ty + 16 + kh][0];
                // cache 8 float2 spans covering all kw for both rows/groups
                const float2 a0 = *(const float2*)(rA + cA);
                const float2 a1 = *(const float2*)(rA + cA + 2);
                const float2 a2 = *(const float2*)(rA + cB);
                const float2 a3 = *(const float2*)(rA + cB + 2);
                const float2 b0 = *(const float2*)(rB + cA);
                const float2 b1 = *(const float2*)(rB + cA + 2);
                const float2 b2 = *(const float2*)(rB + cB);
                const float2 b3 = *(const float2*)(rB + cB + 2);
#pragma unroll
                for (int kw = 0; kw < 3; kw++) {
                    u64 xA0, xA1, xB0, xB1;
                    if (kw == 0) {
                        xA0 = pack2(a0.x, a0.y);  xA1 = pack2(a2.x, a2.y);
                        xB0 = pack2(b0.x, b0.y);  xB1 = pack2(b2.x, b2.y);
                    } else if (kw == 1) {
                        xA0 = pack2(a0.y, a1.x);  xA1 = pack2(a2.y, a3.x);
                        xB0 = pack2(b0.y, b1.x);  xB1 = pack2(b2.y, b3.x);
                    } else {
                        xA0 = pack2(a1.x, a1.y);  xA1 = pack2(a3.x, a3.y);
                        xB0 = pack2(b1.x, b1.y);  xB1 = pack2(b3.x, b3.y);
                    }
                    const int t = kh * 3 + kw;
#pragma unroll
                    for (int c = 0; c < TCO; c++) {
                        const u64 wv = ws2[c][ci][t];   // LDS.64 broadcast
                        ffma2(acc[c][0], xA0, wv);
                        ffma2(acc[c][1], xA1, wv);
                        ffma2(acc[c][2], xB0, wv);
                        ffma2(acc[c][3], xB1, wv);
                    }
                }
            }
        }
        __syncthreads();
    }

    // ---- epilogue: bias + store (float2, aligned) ----
    const int ghA = h0 + ty;
    const int gwA = w0 + cA;
#pragma unroll
    for (int c = 0; c < TCO; c++) {
        const float bv = bias[co0 + c];
        long base = (((long)b * CC + co0 + c) * HH + ghA) * WW + gwA;
        float2 v;
        v = unpack2(acc[c][0]); v.x += bv; v.y += bv; *(float2*)&y[base]               = v;
        v = unpack2(acc[c][1]); v.x += bv; v.y += bv; *(float2*)&y[base + 32]          = v;
        v = unpack2(acc[c][2]); v.x += bv; v.y += bv; *(float2*)&y[base + 16 * WW]     = v;
        v = unpack2(acc[c][3]); v.x += bv; v.y += bv; *(float2*)&y[base + 16 * WW + 32] = v;
    }
}

// ---------------------------------------------------------------------------
// Global average pool
// ---------------------------------------------------------------------------
__global__ __launch_bounds__(256)
void pool_kernel(const float* __restrict__ y)
{
    const int bc = blockIdx.x;
    const float4* p = (const float4*)(y + (long)bc * HW);
    float s = 0.0f;
    for (int i = threadIdx.x; i < HW / 4; i += 256) {
        float4 v = p[i];
        s += v.x + v.y + v.z + v.w;
    }
#pragma unroll
    for (int o = 16; o > 0; o >>= 1)
        s += __shfl_down_sync(0xFFFFFFFFu, s, o);
    __shared__ float red[8];
    if ((threadIdx.x & 31) == 0) red[threadIdx.x >> 5] = s;
    __syncthreads();
    if (threadIdx.x == 0) {
        float t = 0.0f;
#pragma unroll
        for (int i = 0; i < 8; i++) t += red[i];
        g_pool[bc] = t * (1.0f / HW);
    }
}

// ---------------------------------------------------------------------------
// SE FC stack
// ---------------------------------------------------------------------------
__global__ __launch_bounds__(256)
void se_kernel(const float* __restrict__ w1, const float* __restrict__ b1,
               const float* __restrict__ w2, const float* __restrict__ b2)
{
    __shared__ float hbuf[BB][CRED];
    const int tid = threadIdx.x;

    for (int o = tid; o < BB * CRED; o += 256) {
        int b = o / CRED, j = o % CRED;
        float s = b1[j];
        const float* pr = &g_pool[b * CC];
        const float* wr = &w1[j * CC];
        for (int c = 0; c < CC; c++) s = fmaf(pr[c], wr[c], s);
        hbuf[b][j] = fmaxf(s, 0.0f);
    }
    __syncthreads();
    for (int o = tid; o < BB * CC; o += 256) {
        int b = o / CC, c = o % CC;
        float s = b2[c];
        const float* wr = &w2[c * CRED];
#pragma unroll 8
        for (int j = 0; j < CRED; j++) s = fmaf(hbuf[b][j], wr[j], s);
        g_scale[o] = 1.0f / (1.0f + __expf(-s));
    }
}

// ---------------------------------------------------------------------------
// Apply SE scale in place
// ---------------------------------------------------------------------------
__global__ __launch_bounds__(256)
void scale_kernel(float* __restrict__ y)
{
    const long i = (long)blockIdx.x * 256 + threadIdx.x;
    const long bc = (i * 4) >> 14;
    const float sc = g_scale[bc];
    float4* p = (float4*)y;
    float4 v = p[i];
    v.x *= sc; v.y *= sc; v.z *= sc; v.w *= sc;
    p[i] = v;
}

// ---------------------------------------------------------------------------
extern "C" void kernel_launch(void* const* d_in, const int* in_sizes, int n_in,
                              void* d_out, int out_size)
{
    const float* x  = (const float*)d_in[0];
    const float* wd = (const float*)d_in[1];
    const float* bd = (const float*)d_in[2];
    const float* w1 = (const float*)d_in[3];
    const float* b1 = (const float*)d_in[4];
    const float* w2 = (const float*)d_in[5];
    const float* b2 = (const float*)d_in[6];
    float* out = (float*)d_out;

    dim3 cgrid((HH / TH) * (WW / TW), CC / TCO, BB);   // (8, 16, 8)
    conv3x3_kernel<<<cgrid, 256>>>(x, wd, bd, out);
    pool_kernel<<<BB * CC, 256>>>(out);
    se_kernel<<<1, 256>>>(w1, b1, w2, b2);
    scale_kernel<<<(BB * CC * HW) / 4 / 256, 256>>>(out);
}

// round 6
// speedup vs baseline: 2.7472x; 2.7472x over previous
#include <cuda_runtime.h>
#include <cuda_bf16.h>
#include <cstdint>

// Problem constants
#define BB   8
#define CC   256
#define HH   128
#define WW   128
#define CRED 64
#define HW   (HH * WW)

// ---------------------------------------------------------------------------
// Scratch (__device__ globals; small). 16B-aligned: accessed as uint4.
// Weights per tap, chunk-major: [tap][chunk(8)][cout(256)][ci(32)]
// ---------------------------------------------------------------------------
__device__ float g_pool[BB * CC];
__device__ float g_scale[BB * CC];
__device__ __align__(16) __nv_bfloat16 g_wthi[9 * 8 * 256 * 32];
__device__ __align__(16) __nv_bfloat16 g_wtlo[9 * 8 * 256 * 32];

// ---------------------------------------------------------------------------
// Helpers
// ---------------------------------------------------------------------------
__device__ __forceinline__ uint32_t smem_to_u32(const void* p) {
    uint32_t a;
    asm("{ .reg .u64 t; cvta.to.shared.u64 t, %1; cvt.u32.u64 %0, t; }"
        : "=r"(a) : "l"(p));
    return a;
}
#define SW128(off) ((off) ^ (((off) >> 3) & 0x70))

__device__ __forceinline__ void ldsm_x4(uint32_t& r0, uint32_t& r1,
                                        uint32_t& r2, uint32_t& r3, uint32_t addr) {
    asm volatile("ldmatrix.sync.aligned.m8n8.x4.shared.b16 {%0,%1,%2,%3}, [%4];"
                 : "=r"(r0), "=r"(r1), "=r"(r2), "=r"(r3) : "r"(addr));
}
__device__ __forceinline__ void mma16816(float* c, const uint32_t* a, const uint32_t* b) {
    asm volatile(
        "mma.sync.aligned.m16n8k16.row.col.f32.bf16.bf16.f32 "
        "{%0,%1,%2,%3}, {%4,%5,%6,%7}, {%8,%9}, {%0,%1,%2,%3};"
        : "+f"(c[0]), "+f"(c[1]), "+f"(c[2]), "+f"(c[3])
        : "r"(a[0]), "r"(a[1]), "r"(a[2]), "r"(a[3]), "r"(b[0]), "r"(b[1]));
}

// ---------------------------------------------------------------------------
// Pre-pass: weights OIHW fp32 -> [tap][chunk][cout][ci32] bf16 hi/lo
// ---------------------------------------------------------------------------
__global__ __launch_bounds__(256)
void wt_conv_kernel(const float* __restrict__ w)
{
    const int idx = blockIdx.x * 256 + threadIdx.x;   // < 9*256*256
    const int t  = idx >> 16;
    const int n  = (idx >> 8) & 255;
    const int ci = idx & 255;
    const float v = w[((long)n * CC + ci) * 9 + t];
    const __nv_bfloat16 hi = __float2bfloat16(v);
    const float lo = v - __bfloat162float(hi);
    const int dst = (((t * 8 + (ci >> 5)) * 256) + n) * 32 + (ci & 31);
    g_wthi[dst] = hi;
    g_wtlo[dst] = __float2bfloat16(lo);
}

// ---------------------------------------------------------------------------
// Conv via mma.sync (HMMA bf16, fp32 acc), hi/lo split (3 passes).
// Per CTA: (ntile, h, b) -> D[128 pixels, 128 couts].
// 72 stages: tap(9) x ci-chunk(8 of 32).
// SMEM: A[128 rows x 128B] + B[128 rows x 128B] = 32KB static.
//   row layout: bytes 0..63 = hi (k-cols 0..31), bytes 64..127 = lo.
// 8 warps as 2(M) x 4(N): warp tile 64x32.
// ---------------------------------------------------------------------------
__global__ __launch_bounds__(256, 2)
void conv_mma_kernel(const float* __restrict__ x,
                     const float* __restrict__ bias, float* __restrict__ y)
{
    __shared__ __align__(128) unsigned char smA[16384];
    __shared__ __align__(128) unsigned char smB[16384];
    const uint32_t sA = smem_to_u32(smA);
    const uint32_t sB = smem_to_u32(smB);

    const int tid  = threadIdx.x;
    const int wid  = tid >> 5;
    const int lane = tid & 31;
    const int wm   = wid & 1;            // M half
    const int wn   = wid >> 1;           // N quarter
    const int n0   = blockIdx.x * 128;   // cout tile
    const int h    = blockIdx.y;
    const int b    = blockIdx.z;

    float acc[4][4][4];
#pragma unroll
    for (int mt = 0; mt < 4; mt++)
#pragma unroll
        for (int nt = 0; nt < 4; nt++)
#pragma unroll
            for (int r = 0; r < 4; r++) acc[mt][nt][r] = 0.0f;

    // ldmatrix lane-address components
    const int lrow = (lane & 7) + ((lane >> 3) & 1) * 8;   // row within 16
    const int lkcb = ((lane >> 4) * 8) * 2;                // k byte offset within 32B half

    // A-staging thread mapping
    const int am   = tid & 127;          // pixel (w) 0..127
    const int ah   = tid >> 7;           // ci half (0..1)
    // B-staging thread mapping
    const int bq   = tid & 3;            // 16B chunk within 64B row
    const int bn   = tid >> 2;           // cout row 0..63 (x2 iters)

    for (int s = 0; s < 72; s++) {
        const int t   = s >> 3;          // tap
        const int c   = s & 7;           // ci chunk
        const int kh  = t / 3, kw = t % 3;

        __syncthreads();   // WAR: previous stage compute done

        // ---- stage A: 128 pixels x 32 ci, fp32 -> bf16 hi/lo in-kernel ----
        {
            const int hs = h + kh - 1;
            const int wsrc = am + kw - 1;
            const bool ok = (hs >= 0) && (hs < HH) && (wsrc >= 0) && (wsrc < WW);
            const long xbase = ((long)(b * CC + c * 32) * HH + hs) * WW + wsrc;
#pragma unroll
            for (int j = 0; j < 16; j++) {
                const int ci = ah * 16 + j;
                float v = ok ? x[xbase + (long)ci * HW] : 0.0f;
                __nv_bfloat16 hv = __float2bfloat16(v);
                __nv_bfloat16 lv = __float2bfloat16(v - __bfloat162float(hv));
                const uint32_t rb = (uint32_t)(am << 7);
                *(unsigned short*)(smA + SW128(rb + ci * 2))      = __bfloat16_as_ushort(hv);
                *(unsigned short*)(smA + SW128(rb + 64 + ci * 2)) = __bfloat16_as_ushort(lv);
            }
        }
        // ---- stage B: 128 couts x 32 ci from pre-split weights ----
        {
            const long base = (((long)(t * 8 + c) * 256) + n0) * 32;
#pragma unroll
            for (int i2 = 0; i2 < 2; i2++) {
                const int n = bn + i2 * 64;
                const long e = (base + (long)n * 32 + bq * 8) >> 3;   // uint4 index
                uint4 vh = ((const uint4*)g_wthi)[e];
                uint4 vl = ((const uint4*)g_wtlo)[e];
                const uint32_t rb = (uint32_t)(n << 7);
                *(uint4*)(smB + SW128(rb + bq * 16))      = vh;
                *(uint4*)(smB + SW128(rb + 64 + bq * 16)) = vl;
            }
        }
        __syncthreads();

        // ---- compute: 2 k-steps of 16 over the 32-ci chunk ----
#pragma unroll
        for (int kk = 0; kk < 2; kk++) {
            const uint32_t kb = (uint32_t)(kk * 32 + lkcb);   // byte offset in hi half

            uint32_t ahi[4][4];
#pragma unroll
            for (int mt = 0; mt < 4; mt++) {
                const uint32_t rb = (uint32_t)((wm * 64 + mt * 16 + lrow) << 7);
                ldsm_x4(ahi[mt][0], ahi[mt][1], ahi[mt][2], ahi[mt][3],
                        sA + SW128(rb + kb));
            }
            {   // hi*hi
                uint32_t bh[4][2];
#pragma unroll
                for (int np = 0; np < 2; np++) {
                    const uint32_t rb = (uint32_t)((wn * 32 + np * 16 + lrow) << 7);
                    uint32_t r0, r1, r2, r3;
                    ldsm_x4(r0, r1, r2, r3, sB + SW128(rb + kb));
                    bh[2*np][0] = r0; bh[2*np][1] = r2;
                    bh[2*np+1][0] = r1; bh[2*np+1][1] = r3;
                }
#pragma unroll
                for (int mt = 0; mt < 4; mt++)
#pragma unroll
                    for (int nt = 0; nt < 4; nt++) mma16816(acc[mt][nt], ahi[mt], bh[nt]);
            }
            {   // hi*lo
                uint32_t bl[4][2];
#pragma unroll
                for (int np = 0; np < 2; np++) {
                    const uint32_t rb = (uint32_t)((wn * 32 + np * 16 + lrow) << 7);
                    uint32_t r0, r1, r2, r3;
                    ldsm_x4(r0, r1, r2, r3, sB + SW128(rb + 64 + kb));
                    bl[2*np][0] = r0; bl[2*np][1] = r2;
                    bl[2*np+1][0] = r1; bl[2*np+1][1] = r3;
                }
#pragma unroll
                for (int mt = 0; mt < 4; mt++)
#pragma unroll
                    for (int nt = 0; nt < 4; nt++) mma16816(acc[mt][nt], ahi[mt], bl[nt]);
            }
            {   // lo*hi
                uint32_t alo[4][4];
#pragma unroll
                for (int mt = 0; mt < 4; mt++) {
                    const uint32_t rb = (uint32_t)((wm * 64 + mt * 16 + lrow) << 7);
                    ldsm_x4(alo[mt][0], alo[mt][1], alo[mt][2], alo[mt][3],
                            sA + SW128(rb + 64 + kb));
                }
                uint32_t bh[4][2];
#pragma unroll
                for (int np = 0; np < 2; np++) {
                    const uint32_t rb = (uint32_t)((wn * 32 + np * 16 + lrow) << 7);
                    uint32_t r0, r1, r2, r3;
                    ldsm_x4(r0, r1, r2, r3, sB + SW128(rb + kb));
                    bh[2*np][0] = r0; bh[2*np][1] = r2;
                    bh[2*np+1][0] = r1; bh[2*np+1][1] = r3;
                }
#pragma unroll
                for (int mt = 0; mt < 4; mt++)
#pragma unroll
                    for (int nt = 0; nt < 4; nt++) mma16816(acc[mt][nt], alo[mt], bh[nt]);
            }
        }
    }

    // ---- epilogue: bias + store ----
    const int r0 = lane >> 2;
    const int c0 = (lane & 3) * 2;
#pragma unroll
    for (int mt = 0; mt < 4; mt++) {
#pragma unroll
        for (int nt = 0; nt < 4; nt++) {
            const int wpix = wm * 64 + mt * 16 + r0;
            const int co   = n0 + wn * 32 + nt * 8 + c0;
            const float b0 = bias[co], b1 = bias[co + 1];
            long e0 = (((long)b * CC + co) * HH + h) * WW + wpix;
            y[e0]          = acc[mt][nt][0] + b0;
            y[e0 + HW]     = acc[mt][nt][1] + b1;   // co+1
            y[e0 + 8]      = acc[mt][nt][2] + b0;   // wpix+8
            y[e0 + HW + 8] = acc[mt][nt][3] + b1;
        }
    }
}

// ---------------------------------------------------------------------------
// Global average pool
// ---------------------------------------------------------------------------
__global__ __launch_bounds__(256)
void pool_kernel(const float* __restrict__ y)
{
    const int bc = blockIdx.x;
    const float4* p = (const float4*)(y + (long)bc * HW);
    float s = 0.0f;
    for (int i = threadIdx.x; i < HW / 4; i += 256) {
        float4 v = p[i];
        s += v.x + v.y + v.z + v.w;
    }
#pragma unroll
    for (int o = 16; o > 0; o >>= 1)
        s += __shfl_down_sync(0xFFFFFFFFu, s, o);
    __shared__ float red[8];
    if ((threadIdx.x & 31) == 0) red[threadIdx.x >> 5] = s;
    __syncthreads();
    if (threadIdx.x == 0) {
        float t2 = 0.0f;
#pragma unroll
        for (int i = 0; i < 8; i++) t2 += red[i];
        g_pool[bc] = t2 * (1.0f / HW);
    }
}

// ---------------------------------------------------------------------------
// SE FC stack
// ---------------------------------------------------------------------------
__global__ __launch_bounds__(256)
void se_kernel(const float* __restrict__ w1, const float* __restrict__ b1,
               const float* __restrict__ w2, const float* __restrict__ b2)
{
    __shared__ float hbuf[BB][CRED];
    const int tid = threadIdx.x;

    for (int o = tid; o < BB * CRED; o += 256) {
        int b = o / CRED, j = o % CRED;
        float s = b1[j];
        const float* pr = &g_pool[b * CC];
        const float* wr = &w1[j * CC];
        for (int c = 0; c < CC; c++) s = fmaf(pr[c], wr[c], s);
        hbuf[b][j] = fmaxf(s, 0.0f);
    }
    __syncthreads();
    for (int o = tid; o < BB * CC; o += 256) {
        int b = o / CC, c = o % CC;
        float s = b2[c];
        const float* wr = &w2[c * CRED];
#pragma unroll 8
        for (int j = 0; j < CRED; j++) s = fmaf(hbuf[b][j], wr[j], s);
        g_scale[o] = 1.0f / (1.0f + __expf(-s));
    }
}

// ---------------------------------------------------------------------------
// Apply SE scale in place
// ---------------------------------------------------------------------------
__global__ __launch_bounds__(256)
void scale_kernel(float* __restrict__ y)
{
    const long i = (long)blockIdx.x * 256 + threadIdx.x;
    const long bc = (i * 4) >> 14;
    const float sc = g_scale[bc];
    float4* p = (float4*)y;
    float4 v = p[i];
    v.x *= sc; v.y *= sc; v.z *= sc; v.w *= sc;
    p[i] = v;
}

// ---------------------------------------------------------------------------
extern "C" void kernel_launch(void* const* d_in, const int* in_sizes, int n_in,
                              void* d_out, int out_size)
{
    const float* x  = (const float*)d_in[0];
    const float* wd = (const float*)d_in[1];
    const float* bd = (const float*)d_in[2];
    const float* w1 = (const float*)d_in[3];
    const float* b1 = (const float*)d_in[4];
    const float* w2 = (const float*)d_in[5];
    const float* b2 = (const float*)d_in[6];
    float* out = (float*)d_out;

    wt_conv_kernel<<<9 * CC * CC / 256, 256>>>(wd);
    conv_mma_kernel<<<dim3(2, HH, BB), 256>>>(x, bd, out);
    pool_kernel<<<BB * CC, 256>>>(out);
    se_kernel<<<1, 256>>>(w1, b1, w2, b2);
    scale_kernel<<<(BB * CC * HW) / 4 / 256, 256>>>(out);
}

// round 9
// speedup vs baseline: 8.2751x; 3.0122x over previous
#include <cuda_runtime.h>
#include <cuda_fp16.h>
#include <cstdint>

// Problem constants
#define BB   8
#define CC   256
#define HH   128
#define WW   128
#define CRED 64
#define HW   (HH * WW)

// ---------------------------------------------------------------------------
// Scratch (__device__ globals). 16B-aligned (uint4 / cp.async access).
// Weights fp16, chunk-major: [tap][chunk(8)][cout(256)][ci(32)]
// ---------------------------------------------------------------------------
__device__ float g_pool[BB * CC];
__device__ float g_scale[BB * CC];
__device__ __align__(16) __half g_wt[9 * 8 * 256 * 32];

// ---------------------------------------------------------------------------
// Helpers
// ---------------------------------------------------------------------------
__device__ __forceinline__ uint32_t smem_to_u32(const void* p) {
    uint32_t a;
    asm("{ .reg .u64 t; cvta.to.shared.u64 t, %1; cvt.u32.u64 %0, t; }"
        : "=r"(a) : "l"(p));
    return a;
}
#define SW128(off) ((off) ^ (((off) >> 3) & 0x70))

__device__ __forceinline__ void ldsm_x4(uint32_t& r0, uint32_t& r1,
                                        uint32_t& r2, uint32_t& r3, uint32_t addr) {
    asm volatile("ldmatrix.sync.aligned.m8n8.x4.shared.b16 {%0,%1,%2,%3}, [%4];"
                 : "=r"(r0), "=r"(r1), "=r"(r2), "=r"(r3) : "r"(addr));
}
__device__ __forceinline__ void mma16816(float* c, const uint32_t* a, const uint32_t* b) {
    asm volatile(
        "mma.sync.aligned.m16n8k16.row.col.f32.f16.f16.f32 "
        "{%0,%1,%2,%3}, {%4,%5,%6,%7}, {%8,%9}, {%0,%1,%2,%3};"
        : "+f"(c[0]), "+f"(c[1]), "+f"(c[2]), "+f"(c[3])
        : "r"(a[0]), "r"(a[1]), "r"(a[2]), "r"(a[3]), "r"(b[0]), "r"(b[1]));
}
__device__ __forceinline__ void cp_async16(uint32_t dst, const void* src) {
    asm volatile("cp.async.cg.shared.global [%0], [%1], 16;"
                 :: "r"(dst), "l"(src));
}
#define CP_COMMIT() asm volatile("cp.async.commit_group;")
#define CP_WAIT0()  asm volatile("cp.async.wait_group 0;")

// ---------------------------------------------------------------------------
// Pre-pass: weights OIHW fp32 -> [tap][chunk][cout][ci32] fp16; zero g_pool
// ---------------------------------------------------------------------------
__global__ __launch_bounds__(256)
void wt_conv_kernel(const float* __restrict__ w)
{
    const int idx = blockIdx.x * 256 + threadIdx.x;   // < 9*256*256
    if (idx < BB * CC) g_pool[idx] = 0.0f;
    const int t  = idx >> 16;
    const int n  = (idx >> 8) & 255;
    const int ci = idx & 255;
    const float v = w[((long)n * CC + ci) * 9 + t];
    const int dst = (((t * 8 + (ci >> 5)) * 256) + n) * 32 + (ci & 31);
    g_wt[dst] = __float2half_rn(v);
}

// ---------------------------------------------------------------------------
// Conv via mma.sync fp16 (fp32 acc), single pass.
// Per CTA: (ntile, h, b) -> D[128 pixels, 128 couts].
// Loop: chunk(8) x kh(3) x kw(3) = 72 B-stages, 24 A-stages (halo reused 3x).
// smA: 132 rows x 128B (rows 0..129 = wsrc -1..128, 32ci fp16 in bytes 0..63)
// smB: 128 rows x 128B (two stage-parities in byte halves 0..63 / 64..127)
// 8 warps as 2(M) x 4(N): warp tile 64x32. Pool fused in epilogue.
// ---------------------------------------------------------------------------
__global__ __launch_bounds__(256, 2)
void conv_mma_kernel(const float* __restrict__ x,
                     const float* __restrict__ bias, float* __restrict__ y)
{
    __shared__ __align__(128) unsigned char smA[132 * 128];
    __shared__ __align__(128) unsigned char smB[128 * 128];
    const uint32_t sA = smem_to_u32(smA);
    const uint32_t sB = smem_to_u32(smB);

    const int tid  = threadIdx.x;
    const int wid  = tid >> 5;
    const int lane = tid & 31;
    const int wm   = wid & 1;            // M half
    const int wn   = wid >> 1;           // N quarter
    const int n0   = blockIdx.x * 128;   // cout tile
    const int h    = blockIdx.y;
    const int b    = blockIdx.z;

    float acc[4][4][4];
#pragma unroll
    for (int mt = 0; mt < 4; mt++)
#pragma unroll
        for (int nt = 0; nt < 4; nt++)
#pragma unroll
            for (int r = 0; r < 4; r++) acc[mt][nt][r] = 0.0f;

    const int lrow = (lane & 7) + ((lane >> 3) & 1) * 8;
    const int lkcb = ((lane >> 4) * 8) * 2;   // 0 or 16 (bytes)

    // B cp.async mapping: i in {tid, tid+256}; n = i>>2, q = i&3
    // prologue: stage B(0) -> parity 0
    {
        const long base = ((long)(0 * 8 + 0) * 256 + n0) * 32;
#pragma unroll
        for (int r2 = 0; r2 < 2; r2++) {
            int i = tid + r2 * 256;
            int n = i >> 2, q = i & 3;
            cp_async16(sB + SW128((uint32_t)((n << 7) + q * 16)),
                       (const char*)g_wt + (base + (long)n * 32 + q * 8) * 2);
        }
        CP_COMMIT();
    }

    for (int s = 0; s < 72; s++) {
        const int c  = s / 9;            // ci chunk
        const int r9 = s - c * 9;
        const int kh = r9 / 3;
        const int kw = r9 - kh * 3;

        if (kw == 0) {
            __syncthreads();             // prior compute done before A overwrite
            // ---- stage A halo: 130 rows (wsrc -1..128) x 32 ci ----
            const int hs = h + kh - 1;
            const bool hok = (hs >= 0) && (hs < HH);
            for (int task = tid; task < 260; task += 256) {
                const int r  = task >> 1;        // halo row 0..129
                const int hf = task & 1;         // ci half of 16
                const int wsrc = r - 1;
                const bool ok = hok && (wsrc >= 0) && (wsrc < WW);
                const long xb = ((long)(b * CC + c * 32 + hf * 16) * HH + hs) * WW + wsrc;
                const uint32_t rb = (uint32_t)(r << 7) + (uint32_t)(hf * 32);
#pragma unroll
                for (int jj = 0; jj < 8; jj++) {
                    float v0 = ok ? x[xb + (long)(2 * jj) * HW] : 0.0f;
                    float v1 = ok ? x[xb + (long)(2 * jj + 1) * HW] : 0.0f;
                    __half2 hv = __floats2half2_rn(v0, v1);
                    *(uint32_t*)(smA + SW128(rb + jj * 4)) = *(uint32_t*)&hv;
                }
            }
        }

        CP_WAIT0();                      // B(s) arrived
        __syncthreads();                 // staging visible to all

        // ---- prefetch B(s+1) into other parity half ----
        if (s < 71) {
            const int s1 = s + 1;
            const int c1 = s1 / 9;
            const int r91 = s1 - c1 * 9;
            const int t1 = r91;          // tap = kh*3+kw = r9
            const long base = ((long)((t1)*8 + c1) * 256 + n0) * 32;
            const uint32_t par = (uint32_t)((s1 & 1) * 64);
#pragma unroll
            for (int r2 = 0; r2 < 2; r2++) {
                int i = tid + r2 * 256;
                int n = i >> 2, q = i & 3;
                cp_async16(sB + SW128((uint32_t)((n << 7) + par + q * 16)),
                           (const char*)g_wt + (base + (long)n * 32 + q * 8) * 2);
            }
            CP_COMMIT();
        }

        // ---- compute: 2 k-steps of 16 ----
        const uint32_t parB = (uint32_t)((s & 1) * 64);
#pragma unroll
        for (int kk = 0; kk < 2; kk++) {
            const uint32_t kb = (uint32_t)(kk * 32 + lkcb);
            uint32_t a[4][4], bf[4][2];
#pragma unroll
            for (int mt = 0; mt < 4; mt++) {
                const uint32_t rb = (uint32_t)((wm * 64 + mt * 16 + lrow + kw) << 7);
                ldsm_x4(a[mt][0], a[mt][1], a[mt][2], a[mt][3], sA + SW128(rb + kb));
            }
#pragma unroll
            for (int np = 0; np < 2; np++) {
                const uint32_t rb = (uint32_t)((wn * 32 + np * 16 + lrow) << 7);
                uint32_t r0, r1, r2, r3;
                ldsm_x4(r0, r1, r2, r3, sB + SW128(rb + parB + kb));
                bf[2*np][0] = r0;   bf[2*np][1] = r2;
                bf[2*np+1][0] = r1; bf[2*np+1][1] = r3;
            }
#pragma unroll
            for (int mt = 0; mt < 4; mt++)
#pragma unroll
                for (int nt = 0; nt < 4; nt++) mma16816(acc[mt][nt], a[mt], bf[nt]);
        }
    }

    // ---- epilogue: bias + store + fused pool partial sums ----
    const int r0 = lane >> 2;
    const int c0 = (lane & 3) * 2;
#pragma unroll
    for (int nt = 0; nt < 4; nt++) {
        const int co = n0 + wn * 32 + nt * 8 + c0;
        const float b0 = bias[co], b1 = bias[co + 1];
        float sE = 0.0f, sO = 0.0f;
#pragma unroll
        for (int mt = 0; mt < 4; mt++) {
            const int wpix = wm * 64 + mt * 16 + r0;
            long e0 = (((long)b * CC + co) * HH + h) * WW + wpix;
            float v0 = acc[mt][nt][0] + b0;
            float v1 = acc[mt][nt][1] + b1;
            float v2 = acc[mt][nt][2] + b0;
            float v3 = acc[mt][nt][3] + b1;
            y[e0]          = v0;
            y[e0 + HW]     = v1;
            y[e0 + 8]      = v2;
            y[e0 + HW + 8] = v3;
            sE += v0 + v2;
            sO += v1 + v3;
        }
        // reduce across r0 lanes (same co)
#pragma unroll
        for (int o = 4; o < 32; o <<= 1) {
            sE += __shfl_xor_sync(0xFFFFFFFFu, sE, o);
            sO += __shfl_xor_sync(0xFFFFFFFFu, sO, o);
        }
        if (lane < 4) {
            atomicAdd(&g_pool[b * CC + co], sE);
            atomicAdd(&g_pool[b * CC + co + 1], sO);
        }
    }
}

// ---------------------------------------------------------------------------
// SE FC stack: 8 blocks (one per batch), operands cached in smem.
// ---------------------------------------------------------------------------
__global__ __launch_bounds__(256)
void se_kernel(const float* __restrict__ w1, const float* __restrict__ b1,
               const float* __restrict__ w2, const float* __restrict__ b2)
{
    __shared__ float p[CC];
    __shared__ float hbuf[CRED];
    const int b   = blockIdx.x;
    const int tid = threadIdx.x;

    p[tid] = g_pool[b * CC + tid] * (1.0f / HW);
    __syncthreads();

    // FC1: 64 outputs, 4 threads each over 64-length partials
    {
        const int j    = tid >> 2;
        const int part = tid & 3;
        float s = 0.0f;
        const float* wr = &w1[j * CC + part * 64];
        const float* pr = &p[part * 64];
#pragma unroll 16
        for (int c2 = 0; c2 < 64; c2++) s = fmaf(pr[c2], wr[c2], s);
        s += __shfl_xor_sync(0xFFFFFFFFu, s, 1);
        s += __shfl_xor_sync(0xFFFFFFFFu, s, 2);
        if (part == 0) hbuf[j] = fmaxf(s + b1[j], 0.0f);
    }
    __syncthreads();

    // FC2: 256 outputs, one per thread
    {
        float s = b2[tid];
        const float* wr = &w2[tid * CRED];
#pragma unroll 16
        for (int j = 0; j < CRED; j++) s = fmaf(hbuf[j], wr[j], s);
        g_scale[b * CC + tid] = 1.0f / (1.0f + __expf(-s));
    }
}

// ---------------------------------------------------------------------------
// Apply SE scale in place
// ---------------------------------------------------------------------------
__global__ __launch_bounds__(256)
void scale_kernel(float* __restrict__ y)
{
    const long i = (long)blockIdx.x * 256 + threadIdx.x;
    const long bc = (i * 4) >> 14;
    const float sc = g_scale[bc];
    float4* p = (float4*)y;
    float4 v = p[i];
    v.x *= sc; v.y *= sc; v.z *= sc; v.w *= sc;
    p[i] = v;
}

// ---------------------------------------------------------------------------
extern "C" void kernel_launch(void* const* d_in, const int* in_sizes, int n_in,
                              void* d_out, int out_size)
{
    const float* x  = (const float*)d_in[0];
    const float* wd = (const float*)d_in[1];
    const float* bd = (const float*)d_in[2];
    const float* w1 = (const float*)d_in[3];
    const float* b1 = (const float*)d_in[4];
    const float* w2 = (const float*)d_in[5];
    const float* b2 = (const float*)d_in[6];
    float* out = (float*)d_out;

    wt_conv_kernel<<<9 * CC * CC / 256, 256>>>(wd);
    conv_mma_kernel<<<dim3(2, HH, BB), 256>>>(x, bd, out);
    se_kernel<<<BB, 256>>>(w1, b1, w2, b2);
    scale_kernel<<<(BB * CC * HW) / 4 / 256, 256>>>(out);
}

// round 11
// speedup vs baseline: 8.8134x; 1.0650x over previous
#include <cuda_runtime.h>
#include <cuda_fp16.h>
#include <cstdint>

// Problem constants
#define BB   8
#define CC   256
#define HH   128
#define WW   128
#define CRED 64
#define HW   (HH * WW)

// ---------------------------------------------------------------------------
// Scratch (__device__ globals). 16B-aligned (uint4 / cp.async access).
// g_xt: x in NHWC fp16  [b][h][w][ci]          (33.5 MB)
// g_wt: weights fp16    [tap][chunk(8)][cout(256)][ci(32)]
// ---------------------------------------------------------------------------
__device__ float g_pool[BB * CC];
__device__ float g_scale[BB * CC];
__device__ __align__(16) __half g_xt[(size_t)BB * HH * WW * CC];
__device__ __align__(16) __half g_wt[9 * 8 * 256 * 32];

// ---------------------------------------------------------------------------
// Helpers
// ---------------------------------------------------------------------------
__device__ __forceinline__ uint32_t smem_to_u32(const void* p) {
    uint32_t a;
    asm("{ .reg .u64 t; cvta.to.shared.u64 t, %1; cvt.u32.u64 %0, t; }"
        : "=r"(a) : "l"(p));
    return a;
}
#define SW128(off) ((off) ^ (((off) >> 3) & 0x70))

__device__ __forceinline__ void ldsm_x4(uint32_t& r0, uint32_t& r1,
                                        uint32_t& r2, uint32_t& r3, uint32_t addr) {
    asm volatile("ldmatrix.sync.aligned.m8n8.x4.shared.b16 {%0,%1,%2,%3}, [%4];"
                 : "=r"(r0), "=r"(r1), "=r"(r2), "=r"(r3) : "r"(addr));
}
__device__ __forceinline__ void mma16816(float* c, const uint32_t* a, const uint32_t* b) {
    asm volatile(
        "mma.sync.aligned.m16n8k16.row.col.f32.f16.f16.f32 "
        "{%0,%1,%2,%3}, {%4,%5,%6,%7}, {%8,%9}, {%0,%1,%2,%3};"
        : "+f"(c[0]), "+f"(c[1]), "+f"(c[2]), "+f"(c[3])
        : "r"(a[0]), "r"(a[1]), "r"(a[2]), "r"(a[3]), "r"(b[0]), "r"(b[1]));
}
__device__ __forceinline__ void cp_async16(uint32_t dst, const void* src) {
    asm volatile("cp.async.cg.shared.global [%0], [%1], 16;"
                 :: "r"(dst), "l"(src));
}
#define CP_COMMIT() asm volatile("cp.async.commit_group;")
#define CP_WAIT(n)  asm volatile("cp.async.wait_group %0;" :: "n"(n))

// ---------------------------------------------------------------------------
// Pre-pass 1: weights OIHW fp32 -> [tap][chunk][cout][ci32] fp16; zero g_pool
// ---------------------------------------------------------------------------
__global__ __launch_bounds__(256)
void wt_conv_kernel(const float* __restrict__ w)
{
    const int idx = blockIdx.x * 256 + threadIdx.x;   // < 9*256*256
    if (idx < BB * CC) g_pool[idx] = 0.0f;
    const int t  = idx >> 16;
    const int n  = (idx >> 8) & 255;
    const int ci = idx & 255;
    const float v = w[((long)n * CC + ci) * 9 + t];
    const int dst = (((t * 8 + (ci >> 5)) * 256) + n) * 32 + (ci & 31);
    g_wt[dst] = __float2half_rn(v);
}

// ---------------------------------------------------------------------------
// Pre-pass 2: x NCHW fp32 -> NHWC fp16 (smem transpose)
// ---------------------------------------------------------------------------
__global__ __launch_bounds__(256)
void xt_conv_kernel(const float* __restrict__ x)
{
    __shared__ float tile[64][130];
    const int ci0 = blockIdx.x * 64;
    const int h   = blockIdx.y;
    const int b   = blockIdx.z;
    const int tid = threadIdx.x;

#pragma unroll
    for (int i = 0; i < 32; i++) {
        int e = tid + i * 256;            // 0..8191
        int ci = e >> 7, w = e & 127;
        tile[ci][w] = x[(((long)b * CC + ci0 + ci) * HH + h) * WW + w];
    }
    __syncthreads();

    const int w    = tid & 127;
    const int half = tid >> 7;            // ci subrange of 32
    const long ob  = (((long)b * HH + h) * WW + w) * CC + ci0 + half * 32;

    uint32_t pk[16];
#pragma unroll
    for (int j = 0; j < 16; j++) {
        __half2 hv = __floats2half2_rn(tile[half * 32 + 2 * j][w],
                                       tile[half * 32 + 2 * j + 1][w]);
        pk[j] = *(uint32_t*)&hv;
    }
    uint4* op = (uint4*)(g_xt + ob);
#pragma unroll
    for (int j = 0; j < 4; j++)
        op[j] = make_uint4(pk[4*j], pk[4*j+1], pk[4*j+2], pk[4*j+3]);
}

// ---------------------------------------------------------------------------
// Conv via mma.sync fp16 (fp32 acc), fully cp.async double-buffered A and B.
// Per CTA: (ntile, h, b) -> D[128 pixels, 128 couts].
// 72 stages: chunk(8) x kh(3) x kw(3); A restaged every 3 stages (kw reuse).
// smA: 132 rows x 128B — byte halves 0..63 / 64..127 = A parity 0/1
// smB: 128 rows x 128B — byte halves = B parity 0/1
// 8 warps as 2(M) x 4(N): warp tile 64x32. Pool fused in epilogue.
// ---------------------------------------------------------------------------
__device__ __forceinline__ void stage_A(uint32_t sA, int tid, int b, int h,
                                        int sa, uint32_t par)
{
    const int c  = sa / 3;               // ci chunk
    const int kh = sa % 3;
    const int hs = h + kh - 1;
    const bool hok = (hs >= 0) && (hs < HH);
    const long rowbase = ((long)(b * HH + hs) * WW) * CC + (long)c * 32;
    for (int task = tid; task < 520; task += 256) {
        const int r = task >> 2;         // halo row 0..129 (wsrc = r-1)
        const int q = task & 3;          // 16B chunk
        const int wsrc = r - 1;
        const uint32_t dst = sA + SW128((uint32_t)((r << 7) + par + q * 16));
        if (hok && wsrc >= 0 && wsrc < WW) {
            cp_async16(dst, (const char*)(g_xt + rowbase + (long)wsrc * CC) + q * 16);
        } else {
            *(uint4*)(uintptr_t)0 ; // never taken path placeholder (removed below)
        }
    }
}

__global__ __launch_bounds__(256, 2)
void conv_mma_kernel(const float* __restrict__ bias, float* __restrict__ y)
{
    __shared__ __align__(128) unsigned char smA[132 * 128];
    __shared__ __align__(128) unsigned char smB[128 * 128];
    const uint32_t sA = smem_to_u32(smA);
    const uint32_t sB = smem_to_u32(smB);

    const int tid  = threadIdx.x;
    const int wid  = tid >> 5;
    const int lane = tid & 31;
    const int wm   = wid & 1;
    const int wn   = wid >> 1;
    const int n0   = blockIdx.x * 128;
    const int h    = blockIdx.y;
    const int b    = blockIdx.z;

    float acc[4][4][4];
#pragma unroll
    for (int mt = 0; mt < 4; mt++)
#pragma unroll
        for (int nt = 0; nt < 4; nt++)
#pragma unroll
            for (int r = 0; r < 4; r++) acc[mt][nt][r] = 0.0f;

    const int lrow = (lane & 7) + ((lane >> 3) & 1) * 8;
    const int lkcb = ((lane >> 4) * 8) * 2;   // 0 or 16 bytes

    // ---- staging lambdas (inlined manually) ----
    // A stage sa into parity half par (0/64)
    auto do_stage_A = [&](int sa, uint32_t par) {
        const int c  = sa / 3;
        const int kh = sa % 3;
        const int hs = h + kh - 1;
        const bool hok = (hs >= 0) && (hs < HH);
        const long base = ((long)(b * HH + (hok ? hs : 0)) * WW) * CC + (long)c * 32;
        for (int task = tid; task < 520; task += 256) {
            const int r = task >> 2;
            const int q = task & 3;
            const int wsrc = r - 1;
            const uint32_t dst = sA + SW128((uint32_t)((r << 7) + par + q * 16));
            if (hok && wsrc >= 0 && wsrc < WW)
                cp_async16(dst, (const char*)(g_xt + base + (long)wsrc * CC) + q * 16);
            else
                *(uint4*)(smA + SW128((uint32_t)((r << 7) + par + q * 16))) =
                    make_uint4(0, 0, 0, 0);
        }
    };
    // B stage s into parity half par
    auto do_stage_B = [&](int s, uint32_t par) {
        const int c = s / 9;
        const int t = s % 9;             // tap = kh*3+kw
        const long base = ((long)(t * 8 + c) * 256 + n0) * 32;
#pragma unroll
        for (int r2 = 0; r2 < 2; r2++) {
            int i = tid + r2 * 256;
            int n = i >> 2, q = i & 3;
            cp_async16(sB + SW128((uint32_t)((n << 7) + par + q * 16)),
                       (const char*)g_wt + (base + (long)n * 32 + q * 8) * 2);
        }
    };

    // prologue: stage A(0) par0 + B(0) par0 as group G0
    do_stage_A(0, 0);
    do_stage_B(0, 0);
    CP_COMMIT();

    for (int s = 0; s < 72; s++) {
        const int sa = s / 3;
        const int kw = s % 3;

        __syncthreads();                 // compute s-1 done (WAR for prefetch)

        if (s < 71) {
            do_stage_B(s + 1, (uint32_t)(((s + 1) & 1) * 64));
            if (kw == 2)                 // next stage starts new A
                do_stage_A(sa + 1, (uint32_t)(((sa + 1) & 1) * 64));
            CP_COMMIT();
            CP_WAIT(1);                  // stage-s data complete
        } else {
            CP_WAIT(0);
        }
        __syncthreads();                 // staged data visible to all

        const uint32_t parA = (uint32_t)((sa & 1) * 64);
        const uint32_t parB = (uint32_t)((s & 1) * 64);
#pragma unroll
        for (int kk = 0; kk < 2; kk++) {
            const uint32_t kb = (uint32_t)(kk * 32 + lkcb);
            uint32_t a[4][4], bf[4][2];
#pragma unroll
            for (int mt = 0; mt < 4; mt++) {
                const uint32_t rb = (uint32_t)((wm * 64 + mt * 16 + lrow + kw) << 7);
                ldsm_x4(a[mt][0], a[mt][1], a[mt][2], a[mt][3],
                        sA + SW128(rb + parA + kb));
            }
#pragma unroll
            for (int np = 0; np < 2; np++) {
                const uint32_t rb = (uint32_t)((wn * 32 + np * 16 + lrow) << 7);
                uint32_t r0, r1, r2, r3;
                ldsm_x4(r0, r1, r2, r3, sB + SW128(rb + parB + kb));
                bf[2*np][0] = r0;   bf[2*np][1] = r2;
                bf[2*np+1][0] = r1; bf[2*np+1][1] = r3;
            }
#pragma unroll
            for (int mt = 0; mt < 4; mt++)
#pragma unroll
                for (int nt = 0; nt < 4; nt++) mma16816(acc[mt][nt], a[mt], bf[nt]);
        }
    }

    // ---- epilogue: bias + store + fused pool partial sums ----
    const int r0 = lane >> 2;
    const int c0 = (lane & 3) * 2;
#pragma unroll
    for (int nt = 0; nt < 4; nt++) {
        const int co = n0 + wn * 32 + nt * 8 + c0;
        const float b0 = bias[co], b1 = bias[co + 1];
        float sE = 0.0f, sO = 0.0f;
#pragma unroll
        for (int mt = 0; mt < 4; mt++) {
            const int wpix = wm * 64 + mt * 16 + r0;
            long e0 = (((long)b * CC + co) * HH + h) * WW + wpix;
            float v0 = acc[mt][nt][0] + b0;
            float v1 = acc[mt][nt][1] + b1;
            float v2 = acc[mt][nt][2] + b0;
            float v3 = acc[mt][nt][3] + b1;
            y[e0]          = v0;
            y[e0 + HW]     = v1;
            y[e0 + 8]      = v2;
            y[e0 + HW + 8] = v3;
            sE += v0 + v2;
            sO += v1 + v3;
        }
#pragma unroll
        for (int o = 4; o < 32; o <<= 1) {
            sE += __shfl_xor_sync(0xFFFFFFFFu, sE, o);
            sO += __shfl_xor_sync(0xFFFFFFFFu, sO, o);
        }
        if (lane < 4) {
            atomicAdd(&g_pool[b * CC + co], sE);
            atomicAdd(&g_pool[b * CC + co + 1], sO);
        }
    }
}

// ---------------------------------------------------------------------------
// SE FC stack: 8 blocks (one per batch)
// ---------------------------------------------------------------------------
__global__ __launch_bounds__(256)
void se_kernel(const float* __restrict__ w1, const float* __restrict__ b1,
               const float* __restrict__ w2, const float* __restrict__ b2)
{
    __shared__ float p[CC];
    __shared__ float hbuf[CRED];
    const int b   = blockIdx.x;
    const int tid = threadIdx.x;

    p[tid] = g_pool[b * CC + tid] * (1.0f / HW);
    __syncthreads();

    {
        const int j    = tid >> 2;
        const int part = tid & 3;
        float s = 0.0f;
        const float* wr = &w1[j * CC + part * 64];
        const float* pr = &p[part * 64];
#pragma unroll 16
        for (int c2 = 0; c2 < 64; c2++) s = fmaf(pr[c2], wr[c2], s);
        s += __shfl_xor_sync(0xFFFFFFFFu, s, 1);
        s += __shfl_xor_sync(0xFFFFFFFFu, s, 2);
        if (part == 0) hbuf[j] = fmaxf(s + b1[j], 0.0f);
    }
    __syncthreads();

    {
        float s = b2[tid];
        const float* wr = &w2[tid * CRED];
#pragma unroll 16
        for (int j = 0; j < CRED; j++) s = fmaf(hbuf[j], wr[j], s);
        g_scale[b * CC + tid] = 1.0f / (1.0f + __expf(-s));
    }
}

// ---------------------------------------------------------------------------
// Apply SE scale in place
// ---------------------------------------------------------------------------
__global__ __launch_bounds__(256)
void scale_kernel(float* __restrict__ y)
{
    const long i = (long)blockIdx.x * 256 + threadIdx.x;
    const long bc = (i * 4) >> 14;
    const float sc = g_scale[bc];
    float4* p = (float4*)y;
    float4 v = p[i];
    v.x *= sc; v.y *= sc; v.z *= sc; v.w *= sc;
    p[i] = v;
}

// ---------------------------------------------------------------------------
extern "C" void kernel_launch(void* const* d_in, const int* in_sizes, int n_in,
                              void* d_out, int out_size)
{
    const float* x  = (const float*)d_in[0];
    const float* wd = (const float*)d_in[1];
    const float* bd = (const float*)d_in[2];
    const float* w1 = (const float*)d_in[3];
    const float* b1 = (const float*)d_in[4];
    const float* w2 = (const float*)d_in[5];
    const float* b2 = (const float*)d_in[6];
    float* out = (float*)d_out;

    wt_conv_kernel<<<9 * CC * CC / 256, 256>>>(wd);
    xt_conv_kernel<<<dim3(CC / 64, HH, BB), 256>>>(x);
    conv_mma_kernel<<<dim3(2, HH, BB), 256>>>(bd, out);
    se_kernel<<<BB, 256>>>(w1, b1, w2, b2);
    scale_kernel<<<(BB * CC * HW) / 4 / 256, 256>>>(out);
}

// round 13
// speedup vs baseline: 8.8871x; 1.0084x over previous
#include <cuda_runtime.h>
#include <cuda_fp16.h>
#include <cstdint>

// Problem constants
#define BB   8
#define CC   256
#define HH   128
#define WW   128
#define CRED 64
#define HW   (HH * WW)

// ---------------------------------------------------------------------------
// Scratch (__device__ globals). 16B-aligned (uint4 / cp.async access).
// g_xt: x in NHWC fp16  [b][h][w][ci]          (33.5 MB)
// g_wt: weights fp16    [tap][chunk(8)][cout(256)][ci(32)]
// ---------------------------------------------------------------------------
__device__ float g_pool[BB * CC];
__device__ float g_scale[BB * CC];
__device__ __align__(16) __half g_xt[(size_t)BB * HH * WW * CC];
__device__ __align__(16) __half g_wt[9 * 8 * 256 * 32];

// ---------------------------------------------------------------------------
// Helpers
// ---------------------------------------------------------------------------
__device__ __forceinline__ uint32_t smem_to_u32(const void* p) {
    uint32_t a;
    asm("{ .reg .u64 t; cvta.to.shared.u64 t, %1; cvt.u32.u64 %0, t; }"
        : "=r"(a) : "l"(p));
    return a;
}
#define SW128(off) ((off) ^ (((off) >> 3) & 0x70))

__device__ __forceinline__ void ldsm_x4(uint32_t& r0, uint32_t& r1,
                                        uint32_t& r2, uint32_t& r3, uint32_t addr) {
    asm volatile("ldmatrix.sync.aligned.m8n8.x4.shared.b16 {%0,%1,%2,%3}, [%4];"
                 : "=r"(r0), "=r"(r1), "=r"(r2), "=r"(r3) : "r"(addr));
}
__device__ __forceinline__ void mma16816(float* c, const uint32_t* a, const uint32_t* b) {
    asm volatile(
        "mma.sync.aligned.m16n8k16.row.col.f32.f16.f16.f32 "
        "{%0,%1,%2,%3}, {%4,%5,%6,%7}, {%8,%9}, {%0,%1,%2,%3};"
        : "+f"(c[0]), "+f"(c[1]), "+f"(c[2]), "+f"(c[3])
        : "r"(a[0]), "r"(a[1]), "r"(a[2]), "r"(a[3]), "r"(b[0]), "r"(b[1]));
}
__device__ __forceinline__ void cp_async16(uint32_t dst, const void* src) {
    asm volatile("cp.async.cg.shared.global [%0], [%1], 16;"
                 :: "r"(dst), "l"(src));
}
#define CP_COMMIT() asm volatile("cp.async.commit_group;")
#define CP_WAIT(n)  asm volatile("cp.async.wait_group %0;" :: "n"(n))

// ---------------------------------------------------------------------------
// Pre-pass 1: weights OIHW fp32 -> [tap][chunk][cout][ci32] fp16; zero g_pool
// ---------------------------------------------------------------------------
__global__ __launch_bounds__(256)
void wt_conv_kernel(const float* __restrict__ w)
{
    const int idx = blockIdx.x * 256 + threadIdx.x;   // < 9*256*256
    if (idx < BB * CC) g_pool[idx] = 0.0f;
    const int t  = idx >> 16;
    const int n  = (idx >> 8) & 255;
    const int ci = idx & 255;
    const float v = w[((long)n * CC + ci) * 9 + t];
    const int dst = (((t * 8 + (ci >> 5)) * 256) + n) * 32 + (ci & 31);
    g_wt[dst] = __float2half_rn(v);
}

// ---------------------------------------------------------------------------
// Pre-pass 2: x NCHW fp32 -> NHWC fp16 (smem transpose)
// ---------------------------------------------------------------------------
__global__ __launch_bounds__(256)
void xt_conv_kernel(const float* __restrict__ x)
{
    __shared__ float tile[64][130];
    const int ci0 = blockIdx.x * 64;
    const int h   = blockIdx.y;
    const int b   = blockIdx.z;
    const int tid = threadIdx.x;

#pragma unroll
    for (int i = 0; i < 32; i++) {
        int e = tid + i * 256;            // 0..8191
        int ci = e >> 7, w = e & 127;
        tile[ci][w] = x[(((long)b * CC + ci0 + ci) * HH + h) * WW + w];
    }
    __syncthreads();

    const int w    = tid & 127;
    const int half = tid >> 7;            // ci subrange of 32
    const long ob  = (((long)b * HH + h) * WW + w) * CC + ci0 + half * 32;

    uint32_t pk[16];
#pragma unroll
    for (int j = 0; j < 16; j++) {
        __half2 hv = __floats2half2_rn(tile[half * 32 + 2 * j][w],
                                       tile[half * 32 + 2 * j + 1][w]);
        pk[j] = *(uint32_t*)&hv;
    }
    uint4* op = (uint4*)(g_xt + ob);
#pragma unroll
    for (int j = 0; j < 4; j++)
        op[j] = make_uint4(pk[4*j], pk[4*j+1], pk[4*j+2], pk[4*j+3]);
}

// ---------------------------------------------------------------------------
// Conv via mma.sync fp16 (fp32 acc), cp.async double-buffered A and B,
// SINGLE barrier per stage:  wait(G_s) -> sync -> prefetch(s+1) -> compute(s)
// Per CTA: (ntile, h, b) -> D[128 pixels, 128 couts].
// 72 stages: chunk(8) x kh(3) x kw(3); A restaged every 3 stages (kw reuse).
// smA: 132 rows x 128B — byte halves = A parity 0/1
// smB: 128 rows x 128B — byte halves = B parity 0/1
// 8 warps as 2(M) x 4(N): warp tile 64x32. Pool fused in epilogue.
// ---------------------------------------------------------------------------
__global__ __launch_bounds__(256, 2)
void conv_mma_kernel(const float* __restrict__ bias, float* __restrict__ y)
{
    __shared__ __align__(128) unsigned char smA[132 * 128];
    __shared__ __align__(128) unsigned char smB[128 * 128];
    const uint32_t sA = smem_to_u32(smA);
    const uint32_t sB = smem_to_u32(smB);

    const int tid  = threadIdx.x;
    const int wid  = tid >> 5;
    const int lane = tid & 31;
    const int wm   = wid & 1;
    const int wn   = wid >> 1;
    const int n0   = blockIdx.x * 128;
    const int h    = blockIdx.y;
    const int b    = blockIdx.z;

    float acc[4][4][4];
#pragma unroll
    for (int mt = 0; mt < 4; mt++)
#pragma unroll
        for (int nt = 0; nt < 4; nt++)
#pragma unroll
            for (int r = 0; r < 4; r++) acc[mt][nt][r] = 0.0f;

    const int lrow = (lane & 7) + ((lane >> 3) & 1) * 8;
    const int lkcb = ((lane >> 4) * 8) * 2;   // 0 or 16 bytes

    // A stage sa into parity half par (0/64)
    auto do_stage_A = [&](int sa, uint32_t par) {
        const int c  = sa / 3;
        const int kh = sa % 3;
        const int hs = h + kh - 1;
        const bool hok = (hs >= 0) && (hs < HH);
        const long base = ((long)(b * HH + (hok ? hs : 0)) * WW) * CC + (long)c * 32;
        for (int task = tid; task < 520; task += 256) {
            const int r = task >> 2;
            const int q = task & 3;
            const int wsrc = r - 1;
            if (hok && wsrc >= 0 && wsrc < WW)
                cp_async16(sA + SW128((uint32_t)((r << 7) + par + q * 16)),
                           (const char*)(g_xt + base + (long)wsrc * CC) + q * 16);
            else
                *(uint4*)(smA + SW128((uint32_t)((r << 7) + par + q * 16))) =
                    make_uint4(0, 0, 0, 0);
        }
    };
    // B stage s into parity half par
    auto do_stage_B = [&](int s, uint32_t par) {
        const int c = s / 9;
        const int t = s % 9;             // tap = kh*3+kw
        const long base = ((long)(t * 8 + c) * 256 + n0) * 32;
#pragma unroll
        for (int r2 = 0; r2 < 2; r2++) {
            int i = tid + r2 * 256;
            int n = i >> 2, q = i & 3;
            cp_async16(sB + SW128((uint32_t)((n << 7) + par + q * 16)),
                       (const char*)g_wt + (base + (long)n * 32 + q * 8) * 2);
        }
    };

    // prologue: stage A(0) par0 + B(0) par0 as one group
    do_stage_A(0, 0);
    do_stage_B(0, 0);
    CP_COMMIT();

    for (int s = 0; s < 72; s++) {
        const int sa = s / 3;
        const int kw = s % 3;

        CP_WAIT(0);                      // G_s arrived (committed 1 stage ago)
        __syncthreads();                 // data visible + all warps done s-1

        if (s < 71) {                    // prefetch s+1 into other parity
            do_stage_B(s + 1, (uint32_t)(((s + 1) & 1) * 64));
            if (kw == 2)
                do_stage_A(sa + 1, (uint32_t)(((sa + 1) & 1) * 64));
            CP_COMMIT();
        }

        const uint32_t parA = (uint32_t)((sa & 1) * 64);
        const uint32_t parB = (uint32_t)((s & 1) * 64);
#pragma unroll
        for (int kk = 0; kk < 2; kk++) {
            const uint32_t kb = (uint32_t)(kk * 32 + lkcb);
            uint32_t a[4][4], bf[4][2];
#pragma unroll
            for (int mt = 0; mt < 4; mt++) {
                const uint32_t rb = (uint32_t)((wm * 64 + mt * 16 + lrow + kw) << 7);
                ldsm_x4(a[mt][0], a[mt][1], a[mt][2], a[mt][3],
                        sA + SW128(rb + parA + kb));
            }
#pragma unroll
            for (int np = 0; np < 2; np++) {
                const uint32_t rb = (uint32_t)((wn * 32 + np * 16 + lrow) << 7);
                uint32_t r0, r1, r2, r3;
                ldsm_x4(r0, r1, r2, r3, sB + SW128(rb + parB + kb));
                bf[2*np][0] = r0;   bf[2*np][1] = r2;
                bf[2*np+1][0] = r1; bf[2*np+1][1] = r3;
            }
#pragma unroll
            for (int mt = 0; mt < 4; mt++)
#pragma unroll
                for (int nt = 0; nt < 4; nt++) mma16816(acc[mt][nt], a[mt], bf[nt]);
        }
    }

    // ---- epilogue: bias + store + fused pool partial sums ----
    const int r0 = lane >> 2;
    const int c0 = (lane & 3) * 2;
#pragma unroll
    for (int nt = 0; nt < 4; nt++) {
        const int co = n0 + wn * 32 + nt * 8 + c0;
        const float b0 = bias[co], b1 = bias[co + 1];
        float sE = 0.0f, sO = 0.0f;
#pragma unroll
        for (int mt = 0; mt < 4; mt++) {
            const int wpix = wm * 64 + mt * 16 + r0;
            long e0 = (((long)b * CC + co) * HH + h) * WW + wpix;
            float v0 = acc[mt][nt][0] + b0;
            float v1 = acc[mt][nt][1] + b1;
            float v2 = acc[mt][nt][2] + b0;
            float v3 = acc[mt][nt][3] + b1;
            y[e0]          = v0;
            y[e0 + HW]     = v1;
            y[e0 + 8]      = v2;
            y[e0 + HW + 8] = v3;
            sE += v0 + v2;
            sO += v1 + v3;
        }
#pragma unroll
        for (int o = 4; o < 32; o <<= 1) {
            sE += __shfl_xor_sync(0xFFFFFFFFu, sE, o);
            sO += __shfl_xor_sync(0xFFFFFFFFu, sO, o);
        }
        if (lane < 4) {
            atomicAdd(&g_pool[b * CC + co], sE);
            atomicAdd(&g_pool[b * CC + co + 1], sO);
        }
    }
}

// ---------------------------------------------------------------------------
// SE FC stack: 8 blocks (one per batch)
// ---------------------------------------------------------------------------
__global__ __launch_bounds__(256)
void se_kernel(const float* __restrict__ w1, const float* __restrict__ b1,
               const float* __restrict__ w2, const float* __restrict__ b2)
{
    __shared__ float p[CC];
    __shared__ float hbuf[CRED];
    const int b   = blockIdx.x;
    const int tid = threadIdx.x;

    p[tid] = g_pool[b * CC + tid] * (1.0f / HW);
    __syncthreads();

    {
        const int j    = tid >> 2;
        const int part = tid & 3;
        float s = 0.0f;
        const float* wr = &w1[j * CC + part * 64];
        const float* pr = &p[part * 64];
#pragma unroll 16
        for (int c2 = 0; c2 < 64; c2++) s = fmaf(pr[c2], wr[c2], s);
        s += __shfl_xor_sync(0xFFFFFFFFu, s, 1);
        s += __shfl_xor_sync(0xFFFFFFFFu, s, 2);
        if (part == 0) hbuf[j] = fmaxf(s + b1[j], 0.0f);
    }
    __syncthreads();

    {
        float s = b2[tid];
        const float* wr = &w2[tid * CRED];
#pragma unroll 16
        for (int j = 0; j < CRED; j++) s = fmaf(hbuf[j], wr[j], s);
        g_scale[b * CC + tid] = 1.0f / (1.0f + __expf(-s));
    }
}

// ---------------------------------------------------------------------------
// Apply SE scale in place; 2 float4 per thread for higher MLP
// ---------------------------------------------------------------------------
__global__ __launch_bounds__(256)
void scale_kernel(float* __restrict__ y)
{
    const long i0 = ((long)blockIdx.x * 256 + threadIdx.x) * 2;   // float4 idx
    float4* p = (float4*)y;
#pragma unroll
    for (int u = 0; u < 2; u++) {
        const long i = i0 + u;
        const float sc = g_scale[(i * 4) >> 14];
        float4 v = p[i];
        v.x *= sc; v.y *= sc; v.z *= sc; v.w *= sc;
        p[i] = v;
    }
}

// ---------------------------------------------------------------------------
extern "C" void kernel_launch(void* const* d_in, const int* in_sizes, int n_in,
                              void* d_out, int out_size)
{
    const float* x  = (const float*)d_in[0];
    const float* wd = (const float*)d_in[1];
    const float* bd = (const float*)d_in[2];
    const float* w1 = (const float*)d_in[3];
    const float* b1 = (const float*)d_in[4];
    const float* w2 = (const float*)d_in[5];
    const float* b2 = (const float*)d_in[6];
    float* out = (float*)d_out;

    wt_conv_kernel<<<9 * CC * CC / 256, 256>>>(wd);
    xt_conv_kernel<<<dim3(CC / 64, HH, BB), 256>>>(x);
    conv_mma_kernel<<<dim3(2, HH, BB), 256>>>(bd, out);
    se_kernel<<<BB, 256>>>(w1, b1, w2, b2);
    scale_kernel<<<(BB * CC * HW) / 8 / 256, 256>>>(out);
}

// round 15
// speedup vs baseline: 9.8422x; 1.1075x over previous
#include <cuda_runtime.h>
#include <cuda_fp16.h>
#include <cstdint>

// Problem constants
#define BB   8
#define CC   256
#define HH   128
#define WW   128
#define CRED 64
#define HW   (HH * WW)

// ---------------------------------------------------------------------------
// Scratch (__device__ globals). 16B-aligned (uint4 / cp.async access).
// g_xt: x in NHWC fp16  [b][h][w][ci]          (33.5 MB)
// g_wt: weights fp16    [tap][chunk(4)][cout(256)][ci(64)]
// ---------------------------------------------------------------------------
__device__ float g_pool[BB * CC];
__device__ float g_scale[BB * CC];
__device__ __align__(16) __half g_xt[(size_t)BB * HH * WW * CC];
__device__ __align__(16) __half g_wt[9 * 4 * 256 * 64];

// ---------------------------------------------------------------------------
// Helpers
// ---------------------------------------------------------------------------
__device__ __forceinline__ uint32_t smem_to_u32(const void* p) {
    uint32_t a;
    asm("{ .reg .u64 t; cvta.to.shared.u64 t, %1; cvt.u32.u64 %0, t; }"
        : "=r"(a) : "l"(p));
    return a;
}
#define SW128(off) ((off) ^ (((off) >> 3) & 0x70))

__device__ __forceinline__ void ldsm_x4(uint32_t& r0, uint32_t& r1,
                                        uint32_t& r2, uint32_t& r3, uint32_t addr) {
    asm volatile("ldmatrix.sync.aligned.m8n8.x4.shared.b16 {%0,%1,%2,%3}, [%4];"
                 : "=r"(r0), "=r"(r1), "=r"(r2), "=r"(r3) : "r"(addr));
}
__device__ __forceinline__ void mma16816(float* c, const uint32_t* a, const uint32_t* b) {
    asm volatile(
        "mma.sync.aligned.m16n8k16.row.col.f32.f16.f16.f32 "
        "{%0,%1,%2,%3}, {%4,%5,%6,%7}, {%8,%9}, {%0,%1,%2,%3};"
        : "+f"(c[0]), "+f"(c[1]), "+f"(c[2]), "+f"(c[3])
        : "r"(a[0]), "r"(a[1]), "r"(a[2]), "r"(a[3]), "r"(b[0]), "r"(b[1]));
}
__device__ __forceinline__ void cp_async16(uint32_t dst, const void* src) {
    asm volatile("cp.async.cg.shared.global [%0], [%1], 16;"
                 :: "r"(dst), "l"(src));
}
#define CP_COMMIT() asm volatile("cp.async.commit_group;")
#define CP_WAIT(n)  asm volatile("cp.async.wait_group %0;" :: "n"(n))

// ---------------------------------------------------------------------------
// Pre-pass 1: weights OIHW fp32 -> [tap][chunk4][cout][ci64] fp16; zero g_pool
// ---------------------------------------------------------------------------
__global__ __launch_bounds__(256)
void wt_conv_kernel(const float* __restrict__ w)
{
    const int idx = blockIdx.x * 256 + threadIdx.x;   // < 9*256*256
    if (idx < BB * CC) g_pool[idx] = 0.0f;
    const int t  = idx >> 16;
    const int n  = (idx >> 8) & 255;
    const int ci = idx & 255;
    const float v = w[((long)n * CC + ci) * 9 + t];
    const int dst = (((t * 4 + (ci >> 6)) * 256) + n) * 64 + (ci & 63);
    g_wt[dst] = __float2half_rn(v);
}

// ---------------------------------------------------------------------------
// Pre-pass 2: x NCHW fp32 -> NHWC fp16 (smem transpose)
// ---------------------------------------------------------------------------
__global__ __launch_bounds__(256)
void xt_conv_kernel(const float* __restrict__ x)
{
    __shared__ float tile[64][130];
    const int ci0 = blockIdx.x * 64;
    const int h   = blockIdx.y;
    const int b   = blockIdx.z;
    const int tid = threadIdx.x;

#pragma unroll
    for (int i = 0; i < 32; i++) {
        int e = tid + i * 256;            // 0..8191
        int ci = e >> 7, w = e & 127;
        tile[ci][w] = x[(((long)b * CC + ci0 + ci) * HH + h) * WW + w];
    }
    __syncthreads();

    const int w    = tid & 127;
    const int half = tid >> 7;            // ci subrange of 32
    const long ob  = (((long)b * HH + h) * WW + w) * CC + ci0 + half * 32;

    uint32_t pk[16];
#pragma unroll
    for (int j = 0; j < 16; j++) {
        __half2 hv = __floats2half2_rn(tile[half * 32 + 2 * j][w],
                                       tile[half * 32 + 2 * j + 1][w]);
        pk[j] = *(uint32_t*)&hv;
    }
    uint4* op = (uint4*)(g_xt + ob);
#pragma unroll
    for (int j = 0; j < 4; j++)
        op[j] = make_uint4(pk[4*j], pk[4*j+1], pk[4*j+2], pk[4*j+3]);
}

// ---------------------------------------------------------------------------
// Conv via mma.sync fp16 (fp32 acc). K=64 stages, double-buffered cp.async.
// Per CTA: (ntile, h, b) -> D[128 pixels, 128 couts].
// 36 B-stages: chunk(4 of 64ci) x kh(3) x kw(3); A restaged every 3 stages.
// Dynamic smem: B0,B1 = 128 rows x 128B each; A0,A1 = 132 rows x 128B each.
// Single barrier/stage: wait(0) -> sync -> prefetch(s+1) -> compute(s).
// 8 warps as 2(M) x 4(N): warp tile 64x32. Pool fused in epilogue.
// ---------------------------------------------------------------------------
#define BBUF   16384            // B buffer stride (128*128)
#define ABASE  32768            // A buffers start
#define ABUF   16896            // A buffer stride (132*128)
#define SMEMSZ (ABASE + 2 * ABUF)   // 66560

__global__ __launch_bounds__(256, 2)
void conv_mma_kernel(const float* __restrict__ bias, float* __restrict__ y)
{
    extern __shared__ __align__(128) unsigned char smx[];
    const uint32_t s0 = smem_to_u32(smx);

    const int tid  = threadIdx.x;
    const int wid  = tid >> 5;
    const int lane = tid & 31;
    const int wm   = wid & 1;
    const int wn   = wid >> 1;
    const int n0   = blockIdx.x * 128;
    const int h    = blockIdx.y;
    const int b    = blockIdx.z;

    float acc[4][4][4];
#pragma unroll
    for (int mt = 0; mt < 4; mt++)
#pragma unroll
        for (int nt = 0; nt < 4; nt++)
#pragma unroll
            for (int r = 0; r < 4; r++) acc[mt][nt][r] = 0.0f;

    const int lrow = (lane & 7) + ((lane >> 3) & 1) * 8;
    const int lkcb = ((lane >> 4) * 8) * 2;   // 0 or 16 bytes

    // A stage sa (= chunk*3 + kh) into buffer abuf (0/1): 130 rows x 128B
    auto do_stage_A = [&](int sa, int abuf) {
        const int c  = sa / 3;
        const int kh = sa % 3;
        const int hs = h + kh - 1;
        const bool hok = (hs >= 0) && (hs < HH);
        const uint32_t dA = s0 + ABASE + abuf * ABUF;
        const long base = ((long)(b * HH + (hok ? hs : 0)) * WW) * CC + (long)c * 64;
        for (int task = tid; task < 1040; task += 256) {
            const int r = task >> 3;         // halo row 0..129 (wsrc = r-1)
            const int q = task & 7;          // 16B chunk in 128B row
            const int wsrc = r - 1;
            const uint32_t dst = dA + SW128((uint32_t)((r << 7) + q * 16));
            if (hok && wsrc >= 0 && wsrc < WW)
                cp_async16(dst, (const char*)(g_xt + base + (long)wsrc * CC) + q * 16);
            else
                *(uint4*)(smx + (dst - s0)) = make_uint4(0, 0, 0, 0);
        }
    };
    // B stage s (= chunk*9 + tap) into buffer bbuf: 128 rows x 128B
    auto do_stage_B = [&](int s, int bbuf) {
        const int c = s / 9;
        const int t = s % 9;
        const uint32_t dB = s0 + bbuf * BBUF;
        const long base = ((long)(t * 4 + c) * 256 + n0) * 64;
#pragma unroll
        for (int r2 = 0; r2 < 4; r2++) {
            int i = tid + r2 * 256;          // 0..1023
            int n = i >> 3, q = i & 7;
            cp_async16(dB + SW128((uint32_t)((n << 7) + q * 16)),
                       (const char*)g_wt + (base + (long)n * 64 + q * 8) * 2);
        }
    };

    // prologue
    do_stage_A(0, 0);
    do_stage_B(0, 0);
    CP_COMMIT();

    for (int s = 0; s < 36; s++) {
        const int sa = s / 3;
        const int kw = s % 3;

        CP_WAIT(0);                      // stage-s group (committed in s-1)
        __syncthreads();                 // visible + all warps done s-1

        if (s < 35) {
            do_stage_B(s + 1, (s + 1) & 1);
            if (kw == 2)
                do_stage_A(sa + 1, (sa + 1) & 1);
            CP_COMMIT();
        }

        const uint32_t baseA = s0 + ABASE + (sa & 1) * ABUF;
        const uint32_t baseB = s0 + (s & 1) * BBUF;
#pragma unroll
        for (int kk = 0; kk < 4; kk++) {
            const uint32_t kb = (uint32_t)(kk * 32 + lkcb);
            uint32_t a[4][4], bf[4][2];
#pragma unroll
            for (int mt = 0; mt < 4; mt++) {
                const uint32_t rb = (uint32_t)((wm * 64 + mt * 16 + lrow + kw) << 7);
                ldsm_x4(a[mt][0], a[mt][1], a[mt][2], a[mt][3],
                        baseA + SW128(rb + kb));
            }
#pragma unroll
            for (int np = 0; np < 2; np++) {
                const uint32_t rb = (uint32_t)((wn * 32 + np * 16 + lrow) << 7);
                uint32_t r0, r1, r2, r3;
                ldsm_x4(r0, r1, r2, r3, baseB + SW128(rb + kb));
                bf[2*np][0] = r0;   bf[2*np][1] = r2;
                bf[2*np+1][0] = r1; bf[2*np+1][1] = r3;
            }
#pragma unroll
            for (int mt = 0; mt < 4; mt++)
#pragma unroll
                for (int nt = 0; nt < 4; nt++) mma16816(acc[mt][nt], a[mt], bf[nt]);
        }
    }

    // ---- epilogue: bias + store + fused pool partial sums ----
    const int r0 = lane >> 2;
    const int c0 = (lane & 3) * 2;
#pragma unroll
    for (int nt = 0; nt < 4; nt++) {
        const int co = n0 + wn * 32 + nt * 8 + c0;
        const float b0 = bias[co], b1 = bias[co + 1];
        float sE = 0.0f, sO = 0.0f;
#pragma unroll
        for (int mt = 0; mt < 4; mt++) {
            const int wpix = wm * 64 + mt * 16 + r0;
            long e0 = (((long)b * CC + co) * HH + h) * WW + wpix;
            float v0 = acc[mt][nt][0] + b0;
            float v1 = acc[mt][nt][1] + b1;
            float v2 = acc[mt][nt][2] + b0;
            float v3 = acc[mt][nt][3] + b1;
            y[e0]          = v0;
            y[e0 + HW]     = v1;
            y[e0 + 8]      = v2;
            y[e0 + HW + 8] = v3;
            sE += v0 + v2;
            sO += v1 + v3;
        }
#pragma unroll
        for (int o = 4; o < 32; o <<= 1) {
            sE += __shfl_xor_sync(0xFFFFFFFFu, sE, o);
            sO += __shfl_xor_sync(0xFFFFFFFFu, sO, o);
        }
        if (lane < 4) {
            atomicAdd(&g_pool[b * CC + co], sE);
            atomicAdd(&g_pool[b * CC + co + 1], sO);
        }
    }
}

// ---------------------------------------------------------------------------
// SE FC stack: 8 blocks (one per batch)
// ---------------------------------------------------------------------------
__global__ __launch_bounds__(256)
void se_kernel(const float* __restrict__ w1, const float* __restrict__ b1,
               const float* __restrict__ w2, const float* __restrict__ b2)
{
    __shared__ float p[CC];
    __shared__ float hbuf[CRED];
    const int b   = blockIdx.x;
    const int tid = threadIdx.x;

    p[tid] = g_pool[b * CC + tid] * (1.0f / HW);
    __syncthreads();

    {
        const int j    = tid >> 2;
        const int part = tid & 3;
        float s = 0.0f;
        const float* wr = &w1[j * CC + part * 64];
        const float* pr = &p[part * 64];
#pragma unroll 16
        for (int c2 = 0; c2 < 64; c2++) s = fmaf(pr[c2], wr[c2], s);
        s += __shfl_xor_sync(0xFFFFFFFFu, s, 1);
        s += __shfl_xor_sync(0xFFFFFFFFu, s, 2);
        if (part == 0) hbuf[j] = fmaxf(s + b1[j], 0.0f);
    }
    __syncthreads();

    {
        float s = b2[tid];
        const float* wr = &w2[tid * CRED];
#pragma unroll 16
        for (int j = 0; j < CRED; j++) s = fmaf(hbuf[j], wr[j], s);
        g_scale[b * CC + tid] = 1.0f / (1.0f + __expf(-s));
    }
}

// ---------------------------------------------------------------------------
// Apply SE scale in place; 2 float4 per thread
// ---------------------------------------------------------------------------
__global__ __launch_bounds__(256)
void scale_kernel(float* __restrict__ y)
{
    const long i0 = ((long)blockIdx.x * 256 + threadIdx.x) * 2;   // float4 idx
    float4* p = (float4*)y;
#pragma unroll
    for (int u = 0; u < 2; u++) {
        const long i = i0 + u;
        const float sc = g_scale[(i * 4) >> 14];
        float4 v = p[i];
        v.x *= sc; v.y *= sc; v.z *= sc; v.w *= sc;
        p[i] = v;
    }
}

// ---------------------------------------------------------------------------
extern "C" void kernel_launch(void* const* d_in, const int* in_sizes, int n_in,
                              void* d_out, int out_size)
{
    const float* x  = (const float*)d_in[0];
    const float* wd = (const float*)d_in[1];
    const float* bd = (const float*)d_in[2];
    const float* w1 = (const float*)d_in[3];
    const float* b1 = (const float*)d_in[4];
    const float* w2 = (const float*)d_in[5];
    const float* b2 = (const float*)d_in[6];
    float* out = (float*)d_out;

    static int smem_set = 0;
    if (!smem_set) {
        cudaFuncSetAttribute(conv_mma_kernel,
                             cudaFuncAttributeMaxDynamicSharedMemorySize, SMEMSZ);
        smem_set = 1;
    }

    wt_conv_kernel<<<9 * CC * CC / 256, 256>>>(wd);
    xt_conv_kernel<<<dim3(CC / 64, HH, BB), 256>>>(x);
    conv_mma_kernel<<<dim3(2, HH, BB), 256, SMEMSZ>>>(bd, out);
    se_kernel<<<BB, 256>>>(w1, b1, w2, b2);
    scale_kernel<<<(BB * CC * HW) / 8 / 256, 256>>>(out);
}